// round 6
// baseline (speedup 1.0000x reference)
#include <cuda_runtime.h>
#include <stdint.h>

#define BOX 120
#define BOX3 1728000              // 120^3
#define MAXA 512
#define BT_C 44                   // BATCH(4) * NUM_TYPES(11)
#define THREADS 512
#define PLANE (BOX * BOX)         // 14400 floats = 57.6 KB
#define PLANE_F4 (PLANE / 4)      // 3600
#define RCAP 128                  // atoms per plane (mean ~21, P(>128)~0)
#define SMEM_BYTES (PLANE * 4 + RCAP * 16)

extern __shared__ float s_raw[];

// Block = (bt, gx) full plane, dynamic SMEM accumulator:
//   A) issue coords LDG (1 atom/thread), zero smem plane while loads fly,
//      append in-window atoms to record list
//   B) scatter records into smem plane (shared atomics, ~21 atoms x <=25 cells)
//   C) linear smem -> gmem float4 stream (plane contiguous in both)
__global__ void __launch_bounds__(THREADS)
plane_kernel(const float* __restrict__ coords,
             const void* __restrict__ natoms_raw,
             float* __restrict__ out) {
    float*  s_plane = s_raw;
    float4* s_rec   = (float4*)(s_raw + PLANE);   // {ay, az, wx, pack(cy,cz)}
    __shared__ int s_cnt;

    const int b   = blockIdx.x;
    const int bt  = b / BOX;
    const int gx  = b - bt * BOX;
    const int tid = threadIdx.x;

    if (tid == 0) s_cnt = 0;

    // num_atoms may be int64 or int32 (jax x64 flag). Probe element 0: an
    // int32-packed buffer viewed as int64 carries n[1]>=1 in its high word,
    // far outside [1, MAXA].
    const long long* n64 = (const long long*)natoms_raw;
    const int*       n32 = (const int*)natoms_raw;
    long long probe = n64[0];
    int n = (probe >= 1 && probe <= MAXA) ? (int)n64[bt] : n32[bt];

    // ---- Phase A: start coords loads, zero plane under them, then append ----
    const float* cbase = coords + (long long)bt * (3 * MAXA);
    float ax = 0.f, ay = 0.f, az = 0.f;
    bool have = (tid < n);
    if (have) {                      // LDGs issued before the STS stream
        ax = cbase[3 * tid + 0];
        ay = cbase[3 * tid + 1];
        az = cbase[3 * tid + 2];
    }
    __syncthreads();                 // s_cnt initialized

    float4* sp4 = (float4*)s_plane;
    float4 z4 = make_float4(0.f, 0.f, 0.f, 0.f);
    #pragma unroll 7
    for (int i = tid; i < PLANE_F4; i += THREADS)
        sp4[i] = z4;

    if (have) {
        int cx = (int)floorf(ax);
        if ((unsigned)(gx - cx + 2) <= 4u) {       // x cell-window
            int cy = (int)floorf(ay);
            int cz = (int)floorf(az);
            float dx = (float)gx - ax;
            float wx = __expf(-dx * dx);
            int slot = atomicAdd(&s_cnt, 1);
            if (slot < RCAP)
                s_rec[slot] = make_float4(ay, az, wx,
                                          __int_as_float((cy & 0xffff) | (cz << 16)));
        }
    }
    __syncthreads();

    // ---- Phase B: scatter records into smem plane ----
    int cnt = min(s_cnt, RCAP);
    for (int idx = tid; idx < cnt; idx += THREADS) {
        float4 r = s_rec[idx];
        int cyz = __float_as_int(r.w);
        int cy = (int)(short)(cyz & 0xffff);
        int cz = cyz >> 16;
        float wx = r.z;

        float ey[5]; int gyv[5];
        float ez[5]; int gzv[5];
        #pragma unroll
        for (int j = 0; j < 5; ++j) {
            int gy = cy + j - 2;
            gyv[j] = ((unsigned)gy < BOX) ? gy : -1;
            float dy = (float)gy - r.x;
            ey[j] = __expf(-dy * dy);
            int gz = cz + j - 2;
            gzv[j] = ((unsigned)gz < BOX) ? gz : -1;
            float dz = (float)gz - r.y;
            ez[j] = __expf(-dz * dz);
        }
        #pragma unroll
        for (int j = 0; j < 5; ++j) {
            if (gyv[j] < 0) continue;
            float wxy = wx * ey[j];
            float* row = s_plane + gyv[j] * BOX;
            #pragma unroll
            for (int k = 0; k < 5; ++k) {
                if (gzv[k] >= 0)
                    atomicAdd(row + gzv[k], wxy * ez[k]);
            }
        }
    }
    __syncthreads();

    // ---- Phase C: linear smem -> gmem stream ----
    float4* dst4 = (float4*)(out + (long long)bt * BOX3
                                 + (long long)gx * (BOX * BOX));
    #pragma unroll 7
    for (int i = tid; i < PLANE_F4; i += THREADS) {
        float4 v = sp4[i];
        __stcs(dst4 + i, v);
    }
}

extern "C" void kernel_launch(void* const* d_in, const int* in_sizes, int n_in,
                              void* d_out, int out_size) {
    const float* coords = (const float*)d_in[0];
    const void*  natoms = d_in[1];
    float* out = (float*)d_out;

    static bool attr_set = false;
    if (!attr_set) {
        cudaFuncSetAttribute(plane_kernel,
                             cudaFuncAttributeMaxDynamicSharedMemorySize,
                             SMEM_BYTES);
        attr_set = true;
    }
    plane_kernel<<<BT_C * BOX, THREADS, SMEM_BYTES>>>(coords, natoms, out);
}

// round 8
// speedup vs baseline: 1.1035x; 1.1035x over previous
#include <cuda_runtime.h>
#include <stdint.h>

#define BOX 120
#define BOX3 1728000            // 120^3
#define MAXA 512
#define BT_C 44                 // BATCH(4) * NUM_TYPES(11)
#define THREADS 256
#define NWARP (THREADS / 32)
#define HROWS 60                // gy rows per block (half plane)
#define RCAP 64                 // atom records per half-plane (mean ~10)

// Block = (bt, gx, half). Sparse-span SMEM plane accumulator:
//   A) collect nearby atoms; record per-row touched z-span [zmin,zmax]
//   B) zero ONLY span cells in smem (widened to float4 alignment so that
//      every float4 Phase D loads is fully initialized)
//   C) scatter atoms into smem (shared atomics, ~10 atoms x <=25 cells)
//   D) copy: LDS only span float4s; everything else is STG of zero reg
__global__ void __launch_bounds__(THREADS)
plane_kernel(const float* __restrict__ coords,
             const void* __restrict__ natoms_raw,
             float* __restrict__ out) {
    __shared__ float  s_plane[HROWS * BOX];   // 28.8 KB
    __shared__ float4 s_rec[RCAP];            // {ay, az, wx, pack(cy,cz)}
    __shared__ int    s_zmin[HROWS], s_zmax[HROWS];
    __shared__ int    s_cnt;

    const int b    = blockIdx.x;
    const int bt   = b / (BOX * 2);
    const int rem  = b - bt * (BOX * 2);
    const int gx   = rem >> 1;
    const int gy0  = (rem & 1) * HROWS;
    const int tid  = threadIdx.x;
    const int wid  = tid >> 5;
    const int lane = tid & 31;

    if (tid < HROWS) { s_zmin[tid] = BOX; s_zmax[tid] = -1; }
    if (tid == 0) s_cnt = 0;

    // num_atoms may be int64 or int32 (jax x64 flag). Probe element 0: an
    // int32-packed buffer viewed as int64 carries n[1]>=1 in its high word,
    // far outside [1, MAXA].
    const long long* n64 = (const long long*)natoms_raw;
    const int*       n32 = (const int*)natoms_raw;
    long long probe = n64[0];
    int n = (probe >= 1 && probe <= MAXA) ? (int)n64[bt] : n32[bt];
    __syncthreads();

    // ---- Phase A: collect atoms + per-row z-span ----
    const float* cbase = coords + (long long)bt * (3 * MAXA);
    for (int a = tid; a < n; a += THREADS) {
        float ax = cbase[3 * a + 0];
        int cx = (int)floorf(ax);
        if ((unsigned)(gx - cx + 2) > 4u) continue;          // x cell-window
        float ay = cbase[3 * a + 1];
        int cy = (int)floorf(ay);
        int r0 = max(max(cy - 2, gy0), 0);
        int r1 = min(min(cy + 2, gy0 + HROWS - 1), BOX - 1);
        if (r0 > r1) continue;                               // y reach of half
        float az = cbase[3 * a + 2];
        int cz = (int)floorf(az);
        int zlo = max(cz - 2, 0), zhi = min(cz + 2, BOX - 1);
        if (zlo > zhi) continue;
        float dx = (float)gx - ax;
        float wx = __expf(-dx * dx);
        int slot = atomicAdd(&s_cnt, 1);
        if (slot < RCAP)
            s_rec[slot] = make_float4(ay, az, wx,
                                      __int_as_float((cy & 0xffff) | (cz << 16)));
        for (int r = r0; r <= r1; ++r) {
            atomicMin(&s_zmin[r - gy0], zlo);
            atomicMax(&s_zmax[r - gy0], zhi);
        }
    }
    __syncthreads();

    // ---- Phase B: zero span cells, widened to float4 alignment ----
    // zmin&~3 >= 0 and zmax|3 <= 119 (BOX divisible by 4), no clamp needed.
    for (int r = wid; r < HROWS; r += NWARP) {
        int zmax = s_zmax[r];
        if (zmax < 0) continue;
        int zlo = s_zmin[r] & ~3;
        int zhi = zmax | 3;
        for (int z = zlo + lane; z <= zhi; z += 32)
            s_plane[r * BOX + z] = 0.f;
    }
    __syncthreads();

    // ---- Phase C: scatter atoms into smem spans ----
    int cnt = min(s_cnt, RCAP);
    for (int idx = tid; idx < cnt; idx += THREADS) {
        float4 rr = s_rec[idx];
        int cyz = __float_as_int(rr.w);
        int cy = (int)(short)(cyz & 0xffff);
        int cz = cyz >> 16;
        float wx = rr.z;

        float ez[5];
        #pragma unroll
        for (int k = 0; k < 5; ++k) {
            float dz = (float)(cz + k - 2) - rr.y;
            ez[k] = __expf(-dz * dz);
        }
        #pragma unroll
        for (int j = 0; j < 5; ++j) {
            int gy = cy + j - 2;
            if (gy < gy0 || gy >= gy0 + HROWS || (unsigned)gy >= BOX) continue;
            float dy = (float)gy - rr.x;
            float wxy = wx * __expf(-dy * dy);
            float* row = s_plane + (gy - gy0) * BOX;
            #pragma unroll
            for (int k = 0; k < 5; ++k) {
                int gz = cz + k - 2;
                if ((unsigned)gz < BOX)
                    atomicAdd(row + gz, wxy * ez[k]);
            }
        }
    }
    __syncthreads();

    // ---- Phase D: stream out; LDS only where the span lives ----
    float* obase = out + (long long)bt * BOX3
                       + (long long)gx * (BOX * BOX)
                       + gy0 * BOX;
    float4 z4 = make_float4(0.f, 0.f, 0.f, 0.f);
    for (int r = wid; r < HROWS; r += NWARP) {
        int zmin = s_zmin[r], zmax = s_zmax[r];
        if (lane < 30) {
            int z0 = lane * 4;
            float4 v = z4;
            if (z0 + 3 >= zmin && z0 <= zmax)
                v = *(const float4*)&s_plane[r * BOX + z0];
            __stcs((float4*)(obase + r * BOX) + lane, v);
        }
    }
}

extern "C" void kernel_launch(void* const* d_in, const int* in_sizes, int n_in,
                              void* d_out, int out_size) {
    const float* coords = (const float*)d_in[0];
    const void*  natoms = d_in[1];
    float* out = (float*)d_out;
    plane_kernel<<<BT_C * BOX * 2, THREADS>>>(coords, natoms, out);
}

// round 10
// speedup vs baseline: 1.1836x; 1.0725x over previous
#include <cuda_runtime.h>
#include <stdint.h>

#define BOX 120
#define BOX3 1728000            // 120^3
#define MAXA 512
#define BT_C 44                 // BATCH(4) * NUM_TYPES(11)
#define THREADS 256
#define NWARP (THREADS / 32)
#define HROWS 60                // gy rows per block (half plane)
#define ROW_F4 30               // 120/4 float4 per row
#define RCAP 64                 // atom records per half-plane (mean ~6)

// Block = (bt, gx, half). Row-dirty SMEM plane accumulator:
//   A) collect nearby atoms; mark dirty gy-rows (plain idempotent STS)
//   B) zero ONLY dirty rows in smem (warp-uniform branch)
//   C) scatter atoms into smem (shared atomics, ~6 atoms x <=25 cells)
//   D) copy: dirty row -> LDS.128+STG.128; clean row -> STG.128 of zero reg
__global__ void __launch_bounds__(THREADS)
plane_kernel(const float* __restrict__ coords,
             const void* __restrict__ natoms_raw,
             float* __restrict__ out) {
    __shared__ float  s_plane[HROWS * BOX];   // 28.8 KB
    __shared__ float4 s_rec[RCAP];            // {ay, az, wx, pack(cy,cz)}
    __shared__ int    s_dirty[HROWS];
    __shared__ int    s_cnt;

    const int b    = blockIdx.x;
    const int bt   = b / (BOX * 2);
    const int rem  = b - bt * (BOX * 2);
    const int gx   = rem >> 1;
    const int gy0  = (rem & 1) * HROWS;
    const int tid  = threadIdx.x;
    const int wid  = tid >> 5;
    const int lane = tid & 31;

    if (tid < HROWS) s_dirty[tid] = 0;
    if (tid == 0) s_cnt = 0;

    // num_atoms may be int64 or int32 (jax x64 flag). Probe element 0: an
    // int32-packed buffer viewed as int64 carries n[1]>=1 in its high word,
    // far outside [1, MAXA].
    const long long* n64 = (const long long*)natoms_raw;
    const int*       n32 = (const int*)natoms_raw;
    long long probe = n64[0];
    int n = (probe >= 1 && probe <= MAXA) ? (int)n64[bt] : n32[bt];
    __syncthreads();

    // ---- Phase A: collect atoms + mark dirty rows ----
    const float* cbase = coords + (long long)bt * (3 * MAXA);
    for (int a = tid; a < n; a += THREADS) {
        float ax = cbase[3 * a + 0];
        int cx = (int)floorf(ax);
        if ((unsigned)(gx - cx + 2) > 4u) continue;          // x cell-window
        float ay = cbase[3 * a + 1];
        int cy = (int)floorf(ay);
        int r0 = max(max(cy - 2, gy0), 0);
        int r1 = min(min(cy + 2, gy0 + HROWS - 1), BOX - 1);
        if (r0 > r1) continue;                               // y reach of half
        float az = cbase[3 * a + 2];
        int cz = (int)floorf(az);
        float dx = (float)gx - ax;
        float wx = __expf(-dx * dx);
        int slot = atomicAdd(&s_cnt, 1);
        if (slot < RCAP)
            s_rec[slot] = make_float4(ay, az, wx,
                                      __int_as_float((cy & 0xffff) | (cz << 16)));
        for (int r = r0; r <= r1; ++r)
            s_dirty[r - gy0] = 1;                            // idempotent
    }
    __syncthreads();

    // ---- Phase B: zero only dirty rows ----
    float4 z4 = make_float4(0.f, 0.f, 0.f, 0.f);
    for (int r = wid; r < HROWS; r += NWARP) {
        if (s_dirty[r] && lane < ROW_F4)
            ((float4*)&s_plane[r * BOX])[lane] = z4;
    }
    __syncthreads();

    // ---- Phase C: scatter atoms into smem ----
    int cnt = min(s_cnt, RCAP);
    for (int idx = tid; idx < cnt; idx += THREADS) {
        float4 rr = s_rec[idx];
        int cyz = __float_as_int(rr.w);
        int cy = (int)(short)(cyz & 0xffff);
        int cz = cyz >> 16;
        float wx = rr.z;

        float ez[5];
        #pragma unroll
        for (int k = 0; k < 5; ++k) {
            float dz = (float)(cz + k - 2) - rr.y;
            ez[k] = __expf(-dz * dz);
        }
        #pragma unroll
        for (int j = 0; j < 5; ++j) {
            int gy = cy + j - 2;
            if (gy < gy0 || gy >= gy0 + HROWS || (unsigned)gy >= BOX) continue;
            float dy = (float)gy - rr.x;
            float wxy = wx * __expf(-dy * dy);
            float* row = s_plane + (gy - gy0) * BOX;
            #pragma unroll
            for (int k = 0; k < 5; ++k) {
                int gz = cz + k - 2;
                if ((unsigned)gz < BOX)
                    atomicAdd(row + gz, wxy * ez[k]);
            }
        }
    }
    __syncthreads();

    // ---- Phase D: stream out; LDS only for dirty rows ----
    float* obase = out + (long long)bt * BOX3
                       + (long long)gx * (BOX * BOX)
                       + gy0 * BOX;
    for (int r = wid; r < HROWS; r += NWARP) {
        if (lane < ROW_F4) {
            float4 v = z4;
            if (s_dirty[r])
                v = ((const float4*)&s_plane[r * BOX])[lane];
            __stcs((float4*)(obase + r * BOX) + lane, v);
        }
    }
}

extern "C" void kernel_launch(void* const* d_in, const int* in_sizes, int n_in,
                              void* d_out, int out_size) {
    const float* coords = (const float*)d_in[0];
    const void*  natoms = d_in[1];
    float* out = (float*)d_out;
    plane_kernel<<<BT_C * BOX * 2, THREADS>>>(coords, natoms, out);
}

// round 11
// speedup vs baseline: 1.3076x; 1.1048x over previous
#include <cuda_runtime.h>
#include <stdint.h>

#define BOX 120
#define BOX3 1728000            // 120^3
#define MAXA 512
#define BT_C 44                 // BATCH(4) * NUM_TYPES(11)
#define THREADS 256
#define NWARP (THREADS / 32)
#define ROW_F4 30               // 120/4 float4 per row
#define RCAP 128                // atom records per plane (mean ~21)
#define RLCAP 16                // atoms per row list (mean ~0.9)

// Block = (bt, gx) full plane. No SMEM accumulator:
//   A) collect atoms in the gx window; append each atom's index to the
//      row lists of gy = cy-2 .. cy+2 (membership == y-window, no later check)
//   B) warp per row: gather the row's ~0.9 atoms, compute 4 z-voxels in
//      registers, single STG.128 per lane. Clean rows store a zero register.
__global__ void __launch_bounds__(THREADS)
rowlist_kernel(const float* __restrict__ coords,
               const void* __restrict__ natoms_raw,
               float* __restrict__ out) {
    __shared__ float4  s_rec[RCAP];            // {ay, az, wx, cz}
    __shared__ int     s_rowcnt[BOX];
    __shared__ uint8_t s_rowidx[BOX * RLCAP];  // 1-byte atom indices
    __shared__ int     s_cnt;

    const int b    = blockIdx.x;
    const int bt   = b / BOX;
    const int gx   = b - bt * BOX;
    const int tid  = threadIdx.x;
    const int wid  = tid >> 5;
    const int lane = tid & 31;

    if (tid < BOX) s_rowcnt[tid] = 0;
    if (tid == 0) s_cnt = 0;

    // num_atoms may be int64 or int32 (jax x64 flag). Probe element 0: an
    // int32-packed buffer viewed as int64 carries n[1]>=1 in its high word,
    // far outside [1, MAXA].
    const long long* n64 = (const long long*)natoms_raw;
    const int*       n32 = (const int*)natoms_raw;
    long long probe = n64[0];
    int n = (probe >= 1 && probe <= MAXA) ? (int)n64[bt] : n32[bt];
    __syncthreads();

    // ---- Phase A: collect atoms + build per-row index lists ----
    const float* cbase = coords + (long long)bt * (3 * MAXA);
    for (int a = tid; a < n; a += THREADS) {
        float ax = cbase[3 * a + 0];
        int cx = (int)floorf(ax);
        if ((unsigned)(gx - cx + 2) > 4u) continue;      // x cell-window
        float ay = cbase[3 * a + 1];
        float az = cbase[3 * a + 2];
        int cy = (int)floorf(ay);
        int cz = (int)floorf(az);
        float dx = (float)gx - ax;
        float wx = __expf(-dx * dx);
        int slot = atomicAdd(&s_cnt, 1);
        if (slot >= RCAP) continue;
        s_rec[slot] = make_float4(ay, az, wx, __int_as_float(cz));
        int r0 = max(cy - 2, 0), r1 = min(cy + 2, BOX - 1);
        for (int r = r0; r <= r1; ++r) {
            int rs = atomicAdd(&s_rowcnt[r], 1);
            if (rs < RLCAP) s_rowidx[r * RLCAP + rs] = (uint8_t)slot;
        }
    }
    __syncthreads();

    // ---- Phase B: warp per row, register gather, one STG.128 per lane ----
    float* obase = out + (long long)bt * BOX3 + (long long)gx * (BOX * BOX);
    for (int r = wid; r < BOX; r += NWARP) {
        int cnt = min(s_rowcnt[r], RLCAP);
        if (lane < ROW_F4) {
            float v0 = 0.f, v1 = 0.f, v2 = 0.f, v3 = 0.f;
            float fgy = (float)r;
            int z0 = lane * 4;
            float fz0 = (float)z0;
            for (int j = 0; j < cnt; ++j) {
                float4 rec = s_rec[s_rowidx[r * RLCAP + j]];
                float dy = fgy - rec.x;
                float wxy = rec.z * __expf(-dy * dy);
                int cz = __float_as_int(rec.w);
                float dz0 = fz0 - rec.y;
                if ((unsigned)(z0 + 0 - cz + 2) <= 4u) v0 += wxy * __expf(-dz0 * dz0);
                float dz1 = dz0 + 1.f;
                if ((unsigned)(z0 + 1 - cz + 2) <= 4u) v1 += wxy * __expf(-dz1 * dz1);
                float dz2 = dz0 + 2.f;
                if ((unsigned)(z0 + 2 - cz + 2) <= 4u) v2 += wxy * __expf(-dz2 * dz2);
                float dz3 = dz0 + 3.f;
                if ((unsigned)(z0 + 3 - cz + 2) <= 4u) v3 += wxy * __expf(-dz3 * dz3);
            }
            __stcs((float4*)(obase + r * BOX) + lane,
                   make_float4(v0, v1, v2, v3));
        }
    }
}

extern "C" void kernel_launch(void* const* d_in, const int* in_sizes, int n_in,
                              void* d_out, int out_size) {
    const float* coords = (const float*)d_in[0];
    const void*  natoms = d_in[1];
    float* out = (float*)d_out;
    rowlist_kernel<<<BT_C * BOX, THREADS>>>(coords, natoms, out);
}

// round 12
// speedup vs baseline: 1.4065x; 1.0756x over previous
#include <cuda_runtime.h>
#include <stdint.h>

#define BOX 120
#define BOX3 1728000            // 120^3
#define MAXA 512
#define BT_C 44                 // BATCH(4) * NUM_TYPES(11)
#define THREADS 256
#define NWARP (THREADS / 32)
#define ROW_F4 30               // 120/4 float4 per row
#define RCAP 128                // atom records per plane (mean ~21)
#define RLCAP 16                // entries per row list (mean ~0.9)

// Block = (bt, gx) full plane. All transcendentals hoisted to Phase A:
//   A) collect atoms in the gx window. Per atom: compute wx and ez[5] once
//      (ez stored zero-padded so Phase B needs no window branches), and
//      append (slot|cz<<16, wx*ey(row)) to each covered row's list.
//   B) warp per row: per entry, 4 voxels = clamp-index LDS + FFMA. Zero MUFU.
//      One STG.128 per lane; clean rows store a zero register.
__global__ void __launch_bounds__(THREADS)
rowlist_kernel(const float* __restrict__ coords,
               const void* __restrict__ natoms_raw,
               float* __restrict__ out) {
    __shared__ float  s_ez[RCAP * 8];          // [0]=0, [1..5]=ez, [6]=0, [7]=pad
    __shared__ float2 s_ent[BOX * RLCAP];      // {pack(slot,cz), wxy}
    __shared__ int    s_rowcnt[BOX];
    __shared__ int    s_cnt;

    const int b    = blockIdx.x;
    const int bt   = b / BOX;
    const int gx   = b - bt * BOX;
    const int tid  = threadIdx.x;
    const int wid  = tid >> 5;
    const int lane = tid & 31;

    if (tid < BOX) s_rowcnt[tid] = 0;
    if (tid == 0) s_cnt = 0;

    // num_atoms may be int64 or int32 (jax x64 flag). Probe element 0: an
    // int32-packed buffer viewed as int64 carries n[1]>=1 in its high word,
    // far outside [1, MAXA].
    const long long* n64 = (const long long*)natoms_raw;
    const int*       n32 = (const int*)natoms_raw;
    long long probe = n64[0];
    int n = (probe >= 1 && probe <= MAXA) ? (int)n64[bt] : n32[bt];
    __syncthreads();

    // ---- Phase A: collect atoms; hoist ALL exponentials here ----
    const float* cbase = coords + (long long)bt * (3 * MAXA);
    for (int a = tid; a < n; a += THREADS) {
        float ax = cbase[3 * a + 0];
        int cx = (int)floorf(ax);
        if ((unsigned)(gx - cx + 2) > 4u) continue;      // x cell-window
        float ay = cbase[3 * a + 1];
        float az = cbase[3 * a + 2];
        int cy = (int)floorf(ay);
        int cz = (int)floorf(az);
        float dx = (float)gx - ax;
        float wx = __expf(-dx * dx);

        int slot = atomicAdd(&s_cnt, 1);
        if (slot >= RCAP) continue;

        // ez table, zero-padded guards at [0] and [6]
        float* ezp = s_ez + slot * 8;
        ezp[0] = 0.f;
        #pragma unroll
        for (int k = 0; k < 5; ++k) {
            int gz = cz + k - 2;
            float dz = (float)gz - az;
            ezp[k + 1] = ((unsigned)gz < BOX) ? __expf(-dz * dz) : 0.f;
        }
        ezp[6] = 0.f;

        int packed = (slot & 0xffff) | (cz << 16);
        int r0 = max(cy - 2, 0), r1 = min(cy + 2, BOX - 1);
        for (int r = r0; r <= r1; ++r) {
            float dy = (float)r - ay;
            float wxy = wx * __expf(-dy * dy);
            int rs = atomicAdd(&s_rowcnt[r], 1);
            if (rs < RLCAP)
                s_ent[r * RLCAP + rs] =
                    make_float2(__int_as_float(packed), wxy);
        }
    }
    __syncthreads();

    // ---- Phase B: warp per row, clamp-index table gather, STG.128 ----
    float* obase = out + (long long)bt * BOX3 + (long long)gx * (BOX * BOX);
    for (int r = wid; r < BOX; r += NWARP) {
        int cnt = min(s_rowcnt[r], RLCAP);
        if (lane < ROW_F4) {
            float v0 = 0.f, v1 = 0.f, v2 = 0.f, v3 = 0.f;
            int z0 = lane * 4;
            for (int j = 0; j < cnt; ++j) {
                float2 e = s_ent[r * RLCAP + j];
                int bits = __float_as_int(e.x);
                int slot = bits & 0xffff;
                int cz   = bits >> 16;
                float wxy = e.y;
                const float* ezp = s_ez + slot * 8;
                int base = z0 - cz + 3;          // idx for z0; in-window -> [1,5]
                v0 += wxy * ezp[min(max(base + 0, 0), 6)];
                v1 += wxy * ezp[min(max(base + 1, 0), 6)];
                v2 += wxy * ezp[min(max(base + 2, 0), 6)];
                v3 += wxy * ezp[min(max(base + 3, 0), 6)];
            }
            __stcs((float4*)(obase + r * BOX) + lane,
                   make_float4(v0, v1, v2, v3));
        }
    }
}

extern "C" void kernel_launch(void* const* d_in, const int* in_sizes, int n_in,
                              void* d_out, int out_size) {
    const float* coords = (const float*)d_in[0];
    const void*  natoms = d_in[1];
    float* out = (float*)d_out;
    rowlist_kernel<<<BT_C * BOX, THREADS>>>(coords, natoms, out);
}